// round 17
// baseline (speedup 1.0000x reference)
#include <cuda_runtime.h>

#define D 32
#define STEPS 5
#define MAXN 50000
#define MAXE 100000
#define ET 8          // edge types
#define EG 4          // edges per warp (edge kernel)
#define NG 4          // nodes per warp (node kernel)

// ----------------------------- device scratch ------------------------------
__device__ float g_prop[MAXN * D];
__device__ float g_in  [MAXN * D];
__device__ float g_out [MAXN * D];

__device__ int   g_cnt[ET];
__device__ int   g_woff[ET];
__device__ int   g_padBase[ET + 1];
__device__ int   g_padTotal;
__device__ int   g_bucket[MAXE + ET * EG];

__device__ float4 g_Wpk[96 * 32];   // (Wr, Wz, Wt, 0) rows 0..95
__device__ float  g_Wt3[32 * 32];   // Wt rows 64..95 (rp segment)

// ---------------------------------------------------------------------------
// init: prop = emb[token]; zero aggregators; zero type counters; prepack W
// ---------------------------------------------------------------------------
__global__ void ggnn_init(const int* __restrict__ token,
                          const float* __restrict__ emb,
                          const float* __restrict__ Wr,
                          const float* __restrict__ Wz,
                          const float* __restrict__ Wt,
                          int n) {
    int idx = blockIdx.x * blockDim.x + threadIdx.x;
    if (idx < ET) g_cnt[idx] = 0;
    if (idx < 96 * 32) {
        g_Wpk[idx] = make_float4(__ldg(&Wr[idx]), __ldg(&Wz[idx]),
                                 __ldg(&Wt[idx]), 0.f);
        if (idx < 32 * 32) g_Wt3[idx] = __ldg(&Wt[64 * 32 + idx]);
    }
    if (idx >= n * D) return;
    int node = idx >> 5;
    int j    = idx & 31;
    g_prop[idx] = __ldg(&emb[token[node] * D + j]);
    g_in[idx]  = 0.f;
    g_out[idx] = 0.f;
}

// ---------------------------------------------------------------------------
// bucket edges by type
// ---------------------------------------------------------------------------
__global__ void ggnn_count(const int* __restrict__ etype, int e_count) {
    __shared__ int scnt[ET];
    int tid = threadIdx.x;
    if (tid < ET) scnt[tid] = 0;
    __syncthreads();
    int e = blockIdx.x * blockDim.x + tid;
    if (e < e_count) atomicAdd(&scnt[__ldg(&etype[e])], 1);
    __syncthreads();
    if (tid < ET && scnt[tid]) atomicAdd(&g_cnt[tid], scnt[tid]);
}

// warp-parallel prefix + sentinel padding
__global__ void ggnn_prefix() {
    int lane = threadIdx.x;
    int c  = (lane < ET) ? g_cnt[lane] : 0;
    int pc = (c + EG - 1) / EG * EG;
    // inclusive scan of pc across the warp
    int inc = pc;
#pragma unroll
    for (int d = 1; d < 32; d <<= 1) {
        int v = __shfl_up_sync(0xffffffffu, inc, d);
        if (lane >= d) inc += v;
    }
    int base = inc - pc;   // exclusive
    if (lane < ET) {
        g_padBase[lane] = base;
        g_woff[lane] = 0;
        for (int k = c; k < pc; k++) g_bucket[base + k] = -1;  // ≤3 sentinels
    }
    int total = __shfl_sync(0xffffffffu, inc, ET - 1);
    if (lane == 0) { g_padBase[ET] = total; g_padTotal = total; }
}

__global__ void ggnn_scatter(const int* __restrict__ etype, int e_count) {
    __shared__ int scnt[ET], sbase[ET];
    int tid = threadIdx.x;
    if (tid < ET) scnt[tid] = 0;
    __syncthreads();
    int e = blockIdx.x * blockDim.x + tid;
    int t = 0, loc = 0;
    if (e < e_count) {
        t   = __ldg(&etype[e]);
        loc = atomicAdd(&scnt[t], 1);
    }
    __syncthreads();
    if (tid < ET) sbase[tid] = atomicAdd(&g_woff[tid], scnt[tid]);
    __syncthreads();
    if (e < e_count) g_bucket[g_padBase[t] + sbase[t] + loc] = e;
}

// ---------------------------------------------------------------------------
// edge phase: 4 same-type edges per warp; 8 lanes/edge; 4 columns/lane.
// Epilogue uses red.global.add.v4.f32 -> 4x fewer atomic lanes.
// ---------------------------------------------------------------------------
__device__ __forceinline__ void red_add_v4(float* addr, float a, float b,
                                           float c, float d) {
    asm volatile("red.global.add.v4.f32 [%0], {%1,%2,%3,%4};"
                 :: "l"(addr), "f"(a), "f"(b), "f"(c), "f"(d) : "memory");
}

__global__ __launch_bounds__(256)
void ggnn_edge(const int* __restrict__ src,
               const int* __restrict__ dst,
               const float* __restrict__ W_edge) {
    int wid  = (blockIdx.x * blockDim.x + threadIdx.x) >> 5;
    int lane = threadIdx.x & 31;
    int start = wid * EG;
    if (start >= g_padTotal) return;

    // type for this aligned chunk (buckets padded to EG multiples)
    int t = 0;
#pragma unroll
    for (int k = 1; k < ET; k++)
        if (start >= g_padBase[k]) t = k;

    int g = lane >> 3;        // edge slot within warp (0..3)
    int q = lane & 7;         // column-quad (cols 4q..4q+3)

    int e = g_bucket[start + g];
    int s = -1, d = -1;
    float4 h4 = make_float4(0.f, 0.f, 0.f, 0.f);
    if (e >= 0) {
        s  = __ldg(&src[e]);
        d  = __ldg(&dst[e]);
        h4 = *reinterpret_cast<const float4*>(&g_prop[s * D + 4 * q]);
    }

    const float4* __restrict__ W4 =
        reinterpret_cast<const float4*>(W_edge + (size_t)t * (D * D * 2));

    float a00 = 0.f, a01 = 0.f, a02 = 0.f, a03 = 0.f;   // k=0 (in) cols 4q..4q+3
    float a10 = 0.f, a11 = 0.f, a12 = 0.f, a13 = 0.f;   // k=1 (out)

#pragma unroll
    for (int i = 0; i < D; i++) {
        // lane 8*g + (i>>2) holds h[g][i] in component (i&3)
        float v;
        switch (i & 3) {
            case 0: v = h4.x; break;
            case 1: v = h4.y; break;
            case 2: v = h4.z; break;
            default: v = h4.w; break;
        }
        float hv = __shfl_sync(0xffffffffu, v, 8 * g + (i >> 2));
        // W[t][i][4q..4q+3][0..1] = 8 floats = 2 x float4
        float4 wa = __ldg(&W4[i * 16 + 2 * q]);
        float4 wb = __ldg(&W4[i * 16 + 2 * q + 1]);
        a00 = fmaf(hv, wa.x, a00);  a10 = fmaf(hv, wa.y, a10);
        a01 = fmaf(hv, wa.z, a01);  a11 = fmaf(hv, wa.w, a11);
        a02 = fmaf(hv, wb.x, a02);  a12 = fmaf(hv, wb.y, a12);
        a03 = fmaf(hv, wb.z, a03);  a13 = fmaf(hv, wb.w, a13);
    }

    if (s >= 0) {
        red_add_v4(&g_in [d * D + 4 * q], a00, a01, a02, a03);
        red_add_v4(&g_out[s * D + 4 * q], a10, a11, a12, a13);
    }
}

// ---------------------------------------------------------------------------
// node phase: one warp per NG nodes; packed float4 weight rows (Wr,Wz,Wt).
// ---------------------------------------------------------------------------
__device__ __forceinline__ float sigmoidf_(float x) {
    return 1.f / (1.f + __expf(-x));
}

__global__ __launch_bounds__(256)
void ggnn_node(const float* __restrict__ br,
               const float* __restrict__ bz,
               const float* __restrict__ bt,
               float* __restrict__ prop_out,
               int n_count) {
    int wid  = (blockIdx.x * blockDim.x + threadIdx.x) >> 5;
    int lane = threadIdx.x & 31;
    int n0 = wid * NG;
    if (n0 >= n_count) return;

    float fin[NG], fout[NG], p[NG];
#pragma unroll
    for (int g = 0; g < NG; g++) {
        int nid = n0 + g;
        if (nid < n_count) {
            int base = nid * D + lane;
            fin[g]  = g_in[base];   g_in[base]  = 0.f;
            fout[g] = g_out[base];  g_out[base] = 0.f;
            p[g]    = g_prop[base];
        } else { fin[g] = 0.f; fout[g] = 0.f; p[g] = 0.f; }
    }

    float ra[NG], za[NG], ta[NG];
    float brv = __ldg(&br[lane]), bzv = __ldg(&bz[lane]), btv = __ldg(&bt[lane]);
#pragma unroll
    for (int g = 0; g < NG; g++) { ra[g] = brv; za[g] = bzv; ta[g] = btv; }

#pragma unroll
    for (int m = 0; m < 32; m++) {
        float4 w = g_Wpk[m * 32 + lane];
#pragma unroll
        for (int g = 0; g < NG; g++) {
            float c = __shfl_sync(0xffffffffu, fin[g], m);
            ra[g] = fmaf(c, w.x, ra[g]);
            za[g] = fmaf(c, w.y, za[g]);
            ta[g] = fmaf(c, w.z, ta[g]);
        }
    }
#pragma unroll
    for (int m = 0; m < 32; m++) {
        float4 w = g_Wpk[(32 + m) * 32 + lane];
#pragma unroll
        for (int g = 0; g < NG; g++) {
            float c = __shfl_sync(0xffffffffu, fout[g], m);
            ra[g] = fmaf(c, w.x, ra[g]);
            za[g] = fmaf(c, w.y, za[g]);
            ta[g] = fmaf(c, w.z, ta[g]);
        }
    }
#pragma unroll
    for (int m = 0; m < 32; m++) {
        float4 w = g_Wpk[(64 + m) * 32 + lane];
#pragma unroll
        for (int g = 0; g < NG; g++) {
            float c = __shfl_sync(0xffffffffu, p[g], m);
            ra[g] = fmaf(c, w.x, ra[g]);
            za[g] = fmaf(c, w.y, za[g]);
        }
    }

    float rp[NG];
#pragma unroll
    for (int g = 0; g < NG; g++) rp[g] = sigmoidf_(ra[g]) * p[g];

#pragma unroll
    for (int m = 0; m < 32; m++) {
        float w = g_Wt3[m * 32 + lane];
#pragma unroll
        for (int g = 0; g < NG; g++) {
            float c = __shfl_sync(0xffffffffu, rp[g], m);
            ta[g] = fmaf(c, w, ta[g]);
        }
    }

#pragma unroll
    for (int g = 0; g < NG; g++) {
        int nid = n0 + g;
        if (nid < n_count) {
            float z  = sigmoidf_(za[g]);
            float hh = tanhf(ta[g]);
            prop_out[nid * D + lane] = (1.f - z) * p[g] + z * hh;
        }
    }
}

// ---------------------------------------------------------------------------
// launch
// ---------------------------------------------------------------------------
extern "C" void kernel_launch(void* const* d_in, const int* in_sizes, int n_in,
                              void* d_out, int out_size) {
    const int*   token  = (const int*)  d_in[0];
    const int*   etype  = (const int*)  d_in[1];
    const int*   src    = (const int*)  d_in[2];
    const int*   dst    = (const int*)  d_in[3];
    const float* emb    = (const float*)d_in[4];
    const float* W_edge = (const float*)d_in[5];
    const float* W_r    = (const float*)d_in[6];
    const float* b_r    = (const float*)d_in[7];
    const float* W_z    = (const float*)d_in[8];
    const float* b_z    = (const float*)d_in[9];
    const float* W_t    = (const float*)d_in[10];
    const float* b_t    = (const float*)d_in[11];

    int n = in_sizes[0];
    int e = in_sizes[1];
    float* out = (float*)d_out;

    float* prop_sym = nullptr;
    cudaGetSymbolAddress((void**)&prop_sym, g_prop);

    int init_blocks = (n * D + 255) / 256;
    ggnn_init<<<init_blocks, 256>>>(token, emb, W_r, W_z, W_t, n);

    int ecount_blocks = (e + 255) / 256;
    ggnn_count  <<<ecount_blocks, 256>>>(etype, e);
    ggnn_prefix <<<1, 32>>>();
    ggnn_scatter<<<ecount_blocks, 256>>>(etype, e);

    int padMax      = e + ET * (EG - 1);
    int edge_warps  = (padMax + EG - 1) / EG;
    int edge_blocks = (edge_warps * 32 + 255) / 256;

    int node_warps  = (n + NG - 1) / NG;
    int node_blocks = (node_warps * 32 + 255) / 256;

    for (int step = 0; step < STEPS; step++) {
        ggnn_edge<<<edge_blocks, 256>>>(src, dst, W_edge);
        float* po = (step == STEPS - 1) ? out : prop_sym;
        ggnn_node<<<node_blocks, 256>>>(b_r, b_z, b_t, po, n);
    }
}